// round 7
// baseline (speedup 1.0000x reference)
#include <cuda_runtime.h>
#include <cuda_bf16.h>
#include <math.h>

#define B_   8
#define C_   64
#define HW   65536
#define NBC  512
#define RELP 33554432

// ---------------- scratch (__device__ globals; no allocations) ----------------
__device__ float g_sum[NBC], g_sumsq[NBC];
__device__ float g_pool[NBC * 256];
__device__ float g_ap[NBC * 256];
__device__ float g_fpm[B_ * HW];
__device__ float g_hp[B_];
__device__ int   g_msbin[NBC * 256];
__device__ int   g_histms[NBC * 256];
__device__ float g_hms[NBC];
__device__ float g_na[NBC], g_meana[NBC];
__device__ int   g_pabin[B_ * 256];
__device__ int   g_histpa[B_ * 256];
__device__ float g_rowsum[B_ * 257];
__device__ float g_mi[NBC];
__device__ float g_mxv[NBC];
__device__ int   g_amx[NBC];
__device__ int   g_mink[1];
__device__ int   g_order[NBC];
__device__ float g_wsel[NBC];
__device__ float g_psum[NBC * 16], g_psumsq[NBC * 16];
__device__ float g_appart[NBC * 16 * 3 * 16];
__device__ float g_G[256];
__device__ float g_WX[16 * 32];
__device__ float g_gt[513];                  // g(idx-256) table
__device__ float g_fmn[512], g_fmx[512];     // fpm per-block min/max partials
__device__ int   g_histB[B_ * 256];          // per-batch fpm histogram (int, deterministic)

// ---- jax half-pixel bilinear 16->256 weights ----
__device__ __forceinline__ void up_pair(int o, int& j0, float& w0, int& j1, float& w1) {
    int i = o >> 4, r = o & 15;
    if (r < 8) {
        float f = (float)(2 * r + 17) * (1.0f / 32.0f);
        if (i == 0) { j0 = 0; w0 = 1.0f; j1 = 0; w1 = 0.0f; }
        else        { j0 = i - 1; w0 = 1.0f - f; j1 = i; w1 = f; }
    } else {
        float f = (float)(2 * r - 15) * (1.0f / 32.0f);
        if (i == 15) { j0 = 15; w0 = 1.0f; j1 = 15; w1 = 0.0f; }
        else         { j0 = i; w0 = 1.0f - f; j1 = i + 1; w1 = f; }
    }
}
__device__ __forceinline__ float up_w(int o, int j) {
    int j0, j1; float w0, w1;
    up_pair(o, j0, w0, j1, w1);
    float r = 0.0f;
    if (j == j0) r += w0;
    if (j == j1) r += w1;
    return r;
}

__device__ __forceinline__ float gfun(float c) {
    float q = c * (1.0f / 65536.0f);
    return -q * logf(fmaxf(q + 1e-8f, 1e-30f));
}
__device__ __forceinline__ int bin255(float v, float mn, float mx) {
    return (int)(__fmul_rn(__fdiv_rn(v - mn, mx - mn), 255.0f));
}

// ========== K0: tables + zero g_histB ==========
__global__ void tables_kernel() {
    int t = threadIdx.x;
    int i = t >> 4, j = t & 15;
    float g = 0.0f;
    for (int o = 0; o < 256; o++) g += up_w(o, i) * up_w(o, j);
    g_G[t] = g;
    for (int e = t; e < 512; e += 256) {
        int kx = e >> 5, q = e & 31;
        int p = 16 * kx - 8 + q;
        g_WX[e] = (p >= 0 && p < 256) ? up_w(p, kx) : 0.0f;
    }
    for (int e = t; e < 513; e += 256) g_gt[e] = gfun((float)(e - 256));
    for (int e = t; e < B_ * 256; e += 256) g_histB[e] = 0;
}

// ========== K1: fused streaming pass: stats blocks + fpm blocks ==========
__global__ void bigpass_kernel(const float* __restrict__ fp) {
    __shared__ float sv[16 * 257];
    __shared__ float red[256];
    __shared__ float xa[16 * 17];
    __shared__ float wsh[512];
    int blk = blockIdx.x;
    int px = threadIdx.x;
    if (blk < 8192) {
        int bc = blk >> 4, rg = blk & 15;
        const float* base = fp + (size_t)bc * HW + rg * 16 * 256;
        float v[16];
#pragma unroll
        for (int r = 0; r < 16; r++) v[r] = base[r * 256 + px];
        for (int e = px; e < 512; e += 256) wsh[e] = g_WX[e];
        float cs = 0.0f, s2 = 0.0f;
#pragma unroll
        for (int r = 0; r < 16; r++) { cs += v[r]; s2 += v[r] * v[r]; }
#pragma unroll
        for (int r = 0; r < 16; r++) sv[r * 257 + px] = v[r];
        red[px] = cs;
        __syncthreads();
        if (px < 16) {
            float ps = 0.0f;
            for (int q = 0; q < 16; q++) ps += red[px * 16 + q];
            g_pool[bc * 256 + rg * 16 + px] = ps;
        }
        __syncthreads();
        for (int off = 128; off > 0; off >>= 1) { if (px < off) red[px] += red[px + off]; __syncthreads(); }
        if (px == 0) g_psum[bc * 16 + rg] = red[0];
        __syncthreads();
        red[px] = s2; __syncthreads();
        for (int off = 128; off > 0; off >>= 1) { if (px < off) red[px] += red[px + off]; __syncthreads(); }
        if (px == 0) g_psumsq[bc * 16 + rg] = red[0];
        {
            int o = px & 15, kx = px >> 4;
            int p0 = 16 * kx - 8;
            float acc = 0.0f;
#pragma unroll
            for (int q = 0; q < 32; q++) {
                int p = p0 + q;
                int pc = p < 0 ? 0 : (p > 255 ? 255 : p);
                acc += wsh[kx * 32 + q] * sv[o * 257 + pc];
            }
            xa[kx * 17 + o] = acc;
        }
        __syncthreads();
        if (px < 48) {
            int s = px >> 4, kx = px & 15;
            int ky = rg - 1 + s;
            if (ky >= 0 && ky < 16) {
                float acc = 0.0f;
                for (int o = 0; o < 16; o++)
                    acc += up_w(rg * 16 + o, ky) * xa[kx * 17 + o];
                g_appart[((bc * 16 + rg) * 3 + s) * 16 + kx] = acc;
            }
        }
    } else {
        int fblk = blk - 8192;                 // 0..511
        int idx4 = fblk * 256 + px;
        int b = idx4 >> 14;
        int p4 = idx4 & 16383;
        const float4* base = (const float4*)fp + (size_t)b * C_ * 16384 + p4;
        float4 s = make_float4(0.f, 0.f, 0.f, 0.f);
#pragma unroll 16
        for (int c = 0; c < 64; c++) {
            float4 v = base[(size_t)c * 16384];
            s.x += v.x; s.y += v.y; s.z += v.z; s.w += v.w;
        }
        const float inv = 1.0f / 64.0f;
        s.x *= inv; s.y *= inv; s.z *= inv; s.w *= inv;
        ((float4*)g_fpm)[idx4] = s;
        float mn = fminf(fminf(s.x, s.y), fminf(s.z, s.w));
        float mx = fmaxf(fmaxf(s.x, s.y), fmaxf(s.z, s.w));
        red[px] = mn;
        sv[px] = mx;
        __syncthreads();
        for (int off = 128; off > 0; off >>= 1) {
            if (px < off) {
                red[px] = fminf(red[px], red[px + off]);
                sv[px] = fmaxf(sv[px], sv[px + off]);
            }
            __syncthreads();
        }
        if (px == 0) { g_fmn[fblk] = red[0]; g_fmx[fblk] = sv[0]; }
    }
}

// ========== K2: combine stats partials ==========
__global__ void reduce_kernel() {
    int bc = blockIdx.x, t = threadIdx.x;
    if (t == 0) {
        float s = 0.0f;
        for (int r = 0; r < 16; r++) s += g_psum[bc * 16 + r];
        g_sum[bc] = s;
    } else if (t == 32) {
        float s = 0.0f;
        for (int r = 0; r < 16; r++) s += g_psumsq[bc * 16 + r];
        g_sumsq[bc] = s;
    }
    int ky = t >> 4;
    float acc = 0.0f;
    if (ky - 1 >= 0) acc += g_appart[((bc * 16 + ky - 1) * 3 + 2) * 16 + (t & 15)];
    acc += g_appart[((bc * 16 + ky) * 3 + 1) * 16 + (t & 15)];
    if (ky + 1 < 16)  acc += g_appart[((bc * 16 + ky + 1) * 3 + 0) * 16 + (t & 15)];
    g_ap[bc * 256 + t] = acc;
}

// ========== K3: parallel per-batch fpm histogram (64 blocks x 1024 elems) ====
__global__ void histB_kernel() {
    int blk = blockIdx.x;                  // 512 blocks
    int b = blk >> 6, chunk = blk & 63;
    int t = threadIdx.x;
    __shared__ float ra[64], rb[64];
    __shared__ int hist[256];
    if (t < 64) { ra[t] = g_fmn[b * 64 + t]; rb[t] = g_fmx[b * 64 + t]; }
    hist[t] = 0;
    __syncthreads();
    if (t < 32) { ra[t] = fminf(ra[t], ra[t + 32]); rb[t] = fmaxf(rb[t], rb[t + 32]); }
    __syncthreads();
    if (t < 16) { ra[t] = fminf(ra[t], ra[t + 16]); rb[t] = fmaxf(rb[t], rb[t + 16]); }
    __syncthreads();
    if (t < 8) { ra[t] = fminf(ra[t], ra[t + 8]); rb[t] = fmaxf(rb[t], rb[t + 8]); }
    __syncthreads();
    if (t < 4) { ra[t] = fminf(ra[t], ra[t + 4]); rb[t] = fmaxf(rb[t], rb[t + 4]); }
    __syncthreads();
    if (t < 2) { ra[t] = fminf(ra[t], ra[t + 2]); rb[t] = fmaxf(rb[t], rb[t + 2]); }
    __syncthreads();
    if (t == 0) { ra[0] = fminf(ra[0], ra[1]); rb[0] = fmaxf(rb[0], rb[1]); }
    __syncthreads();
    float mn = ra[0], mx = rb[0];
    const float* base = g_fpm + b * HW + chunk * 1024;   // 64 chunks x 1024 = 65536
#pragma unroll
    for (int i = 0; i < 4; i++) {
        float v = base[i * 256 + t];
        atomicAdd(&hist[bin255(v, mn, mx)], 1);
    }
    __syncthreads();
    if (hist[t] > 0) atomicAdd(&g_histB[b * 256 + t], hist[t]);
}

// ========== K4: ms binning + entropy + Gram moments ==========
__global__ void ms_kernel(const float* __restrict__ fms) {
    int bc = blockIdx.x, t = threadIdx.x;
    __shared__ float sv[256];
    __shared__ float ra[256], rb[256];
    __shared__ int hist[256];
    __shared__ float Gsh[256], Nsh[256];
    float v = fms[bc * 256 + t];
    sv[t] = v;
    Gsh[t] = g_G[t];
    ra[t] = v; rb[t] = v; __syncthreads();
    for (int off = 128; off > 0; off >>= 1) {
        if (t < off) { ra[t] = fminf(ra[t], ra[t + off]); rb[t] = fmaxf(rb[t], rb[t + off]); }
        __syncthreads();
    }
    float mn = ra[0], mx = rb[0];
    int bin = bin255(v, mn, mx);
    g_msbin[bc * 256 + t] = bin;
    hist[t] = 0; __syncthreads();
    atomicAdd(&hist[bin], 1); __syncthreads();
    g_histms[bc * 256 + t] = hist[t];
    float p = hist[t] * (1.0f / 256.0f);
    ra[t] = -p * logf(p + 1e-8f);
    __syncthreads();
    for (int off = 128; off > 0; off >>= 1) { if (t < off) ra[t] += ra[t + off]; __syncthreads(); }
    if (t == 0) g_hms[bc] = ra[0];
    __syncthreads();
    int i = t >> 4, j = t & 15;
    float n = 0.0f;
#pragma unroll
    for (int k = 0; k < 16; k++) n += sv[i * 16 + k] * Gsh[k * 16 + j];
    Nsh[t] = n;
    __syncthreads();
    float pp = 0.0f;
#pragma unroll
    for (int k = 0; k < 16; k++) pp += Nsh[i * 16 + k] * sv[j * 16 + k];
    ra[t] = Gsh[t] * pp;
    rb[t] = sv[t];
    __syncthreads();
    for (int off = 128; off > 0; off >>= 1) {
        if (t < off) { ra[t] += ra[t + off]; rb[t] += rb[t + off]; }
        __syncthreads();
    }
    if (t == 0) {
        float SU2 = ra[0];
        float SU = 256.0f * rb[0];
        g_meana[bc] = SU * (1.0f / 65536.0f);
        g_na[bc] = __fsqrt_rn(SU2 - SU * SU * (1.0f / 65536.0f));
    }
}

// ========== K5: f_p_a binning + rowsum table + hp entropy (merged) ==========
__global__ void parow_kernel() {
    int b = blockIdx.x, t = threadIdx.x;
    __shared__ float ra[256], rb[256];
    __shared__ int hist[256];
    __shared__ float gts[513];
    float val = 0.0f;
    for (int c = 0; c < 64; c++) val += g_pool[(b * 64 + c) * 256 + t] * (1.0f / 256.0f);
    val *= (1.0f / 64.0f);
    for (int e = t; e < 513; e += 256) gts[e] = g_gt[e];
    ra[t] = val; rb[t] = val; __syncthreads();
    for (int off = 128; off > 0; off >>= 1) {
        if (t < off) { ra[t] = fminf(ra[t], ra[t + off]); rb[t] = fmaxf(rb[t], rb[t + off]); }
        __syncthreads();
    }
    float mn = ra[0], mx = rb[0];
    int bin = bin255(val, mn, mx);
    g_pabin[b * 256 + t] = bin;
    hist[t] = 0; __syncthreads();
    atomicAdd(&hist[bin], 1); __syncthreads();
    g_histpa[b * 256 + t] = hist[t];
    // hp entropy from the global fpm histogram
    float pB = (float)g_histB[b * 256 + t] * (1.0f / 65536.0f);
    ra[t] = -pB * logf(pB + 1e-8f);
    __syncthreads();
    for (int off = 128; off > 0; off >>= 1) { if (t < off) ra[t] += ra[t + off]; __syncthreads(); }
    if (t == 0) g_hp[b] = ra[0];
    __syncthreads();
    // rowsum[u] = sum_j g(256 - u - hp[j]) = sum_j gts[512 - u - hist[j]]
    float acc = 0.0f;
    for (int j = 0; j < 256; j++) acc += gts[512 - t - hist[j]];
    g_rowsum[b * 257 + t] = acc;
    if (t == 0) {
        float a2 = 0.0f;
        for (int j = 0; j < 256; j++) a2 += gts[256 - hist[j]];
        g_rowsum[b * 257 + 256] = a2;
    }
}

// ========== K6: joint entropy + mi ==========
__global__ void joint_kernel() {
    int bc = blockIdx.x, t = threadIdx.x;
    int b = bc >> 6;
    __shared__ int keys[256];
    __shared__ float red[256];
    __shared__ float gts[513];
    int u = g_msbin[bc * 256 + t];
    int v = g_pabin[b * 256 + t];
    keys[t] = u * 256 + v;
    for (int e = t; e < 513; e += 256) gts[e] = g_gt[e];
    __syncthreads();
    float acc = g_rowsum[b * 257 + g_histms[bc * 256 + t]];
    int my = keys[t], J = 0; bool first = true;
    for (int q = 0; q < 256; q++) {
        int k = keys[q];
        if (k == my) { J++; if (q < t) first = false; }
    }
    if (first) {
        int hm = g_histms[bc * 256 + u];
        int hp = g_histpa[b * 256 + v];
        int cold = 256 - hm - hp;
        acc += gts[cold + 2 * J + 256] - gts[cold + 256];
    }
    red[t] = acc; __syncthreads();
    for (int off = 128; off > 0; off >>= 1) { if (t < off) red[t] += red[t + off]; __syncthreads(); }
    if (t == 0) g_mi[bc] = g_hp[b] + g_hms[bc] - red[0];
}

// ========== K7: softmax(mi) and rel_ms output ==========
__global__ void relms_kernel(const float* __restrict__ fms, float* __restrict__ out) {
    int b = blockIdx.x, t = threadIdx.x;
    __shared__ float mi[64];
    if (t < 64) mi[t] = g_mi[b * 64 + t];
    __syncthreads();
    if (t == 0) {
        float mx = mi[0];
        for (int c = 1; c < 64; c++) mx = fmaxf(mx, mi[c]);
        float s = 0.0f;
        for (int c = 0; c < 64; c++) { mi[c] = expf(mi[c] - mx); s += mi[c]; }
        float inv = 1.0f / s;
        for (int c = 0; c < 64; c++) mi[c] *= inv;
    }
    __syncthreads();
    for (int c = 0; c < 64; c++) {
        int i = (b * 64 + c) * 256 + t;
        float vv = fms[i];
        out[RELP + i] = vv + vv * mi[c];
    }
}

// ========== K8: similarity max/argmax (coalesced shared tiles, 2 halves) =====
__global__ void smat_kernel(const float* __restrict__ fms) {
    int bc = blockIdx.x, t = threadIdx.x;   // 256 threads
    int b = bc >> 6;
    __shared__ float ms[256];
    __shared__ float sap[32 * 257];
    __shared__ float val[64];
    ms[t] = fms[bc * 256 + t];
    float meana = g_meana[bc];
    for (int h = 0; h < 2; h++) {
        __syncthreads();
        for (int i = 0; i < 32; i++)
            sap[i * 257 + t] = g_ap[(size_t)(b * 64 + h * 32 + i) * 256 + t];
        __syncthreads();
        if ((t >> 5) == h && t < 64) {
            int row = t & 31;
            float dot = 0.0f;
#pragma unroll 8
            for (int k = 0; k < 256; k++) dot += ms[k] * sap[row * 257 + k];
            val[t] = dot - meana * g_sum[b * 64 + t];
        }
    }
    __syncthreads();
    if (t == 0) {
        float mx = val[0]; int am = 0;
        for (int d = 1; d < 64; d++) if (val[d] > mx) { mx = val[d]; am = d; }
        float nb = __fsqrt_rn(g_sumsq[bc] - g_sum[bc] * g_sum[bc] * (1.0f / 65536.0f));
        float den = __fmul_rn(g_na[bc] * nb, 0.01f);
        g_mxv[bc] = __fdiv_rn(mx, den);
        g_amx[bc] = am;
    }
}

// ========== K9: groups + min_k + sort + selection softmax (merged) ==========
__global__ void grpsel_kernel() {
    int t = threadIdx.x;                 // 512 threads
    int b = t >> 6, i = t & 63;
    __shared__ float sc[8][64], gsh[8][64], sortedv[8][64];
    __shared__ int csh[8][64];
    __shared__ int uniq[8];
    __shared__ int mk;
    sc[b][i] = g_mxv[b * 64 + i];
    gsh[b][i] = 0.0f; csh[b][i] = 0;
    __syncthreads();
    if (i == 0) {
        float mx = sc[b][0];
        for (int c = 1; c < 64; c++) mx = fmaxf(mx, sc[b][c]);
        float s = 0.0f;
        for (int c = 0; c < 64; c++) { sc[b][c] = expf(sc[b][c] - mx); s += sc[b][c]; }
        float inv = 1.0f / s;
        for (int c = 0; c < 64; c++) sc[b][c] *= inv;
    }
    __syncthreads();
    int idx = g_amx[b * 64 + i];
    atomicAdd(&gsh[b][idx], sc[b][i]);
    atomicAdd(&csh[b][idx], 1);
    __syncthreads();
    if (i == 0) {
        int u = 0;
        for (int j = 0; j < 64; j++) u += (csh[b][j] > 0) ? 1 : 0;
        uniq[b] = u;
    }
    __syncthreads();
    if (t == 0) {
        int m = uniq[0];
        for (int q = 1; q < 8; q++) m = min(m, uniq[q]);
        mk = (m + 1) >> 1;
        g_mink[0] = mk;
    }
    float vi = gsh[b][i];
    int r = 0;
    for (int j = 0; j < 64; j++) {
        float vj = gsh[b][j];
        if (vj > vi || (vj == vi && j < i)) r++;
    }
    g_order[b * 64 + r] = i;
    sortedv[b][r] = vi;
    __syncthreads();
    if (i == 0) {
        int m = mk;
        float mx = sortedv[b][0];
        float s = 0.0f;
        for (int q = 0; q < m; q++) { float e = expf(sortedv[b][q] - mx); sortedv[b][q] = e; s += e; }
        float inv = 1.0f / s;
        for (int q = 0; q < m; q++) g_wsel[b * 64 + q] = sortedv[b][q] * inv;
        for (int q = m; q < 64; q++) g_wsel[b * 64 + q] = 0.0f;
    }
}

// ========== K10: fused mask + rel_p output (float4) ==========
__global__ void final_kernel(const float* __restrict__ fp, float* __restrict__ out) {
    int blk = blockIdx.x;
    int b = blk >> 6;
    int p4 = ((blk & 63) << 8) | threadIdx.x;
    __shared__ int mk;
    __shared__ int ord[32];
    __shared__ float w[32];
    if (threadIdx.x == 0) mk = g_mink[0];
    if (threadIdx.x < 32) {
        ord[threadIdx.x] = g_order[b * 64 + threadIdx.x];
        w[threadIdx.x] = g_wsel[b * 64 + threadIdx.x];
    }
    __syncthreads();
    const float4* base = (const float4*)fp + (size_t)b * C_ * 16384;
    float4 m = make_float4(0.f, 0.f, 0.f, 0.f);
    int mkk = mk;
    for (int r = 0; r < mkk; r++) {
        float4 v = base[(size_t)ord[r] * 16384 + p4];
        float ww = w[r];
        m.x += ww / (1.0f + expf(-v.x));
        m.y += ww / (1.0f + expf(-v.y));
        m.z += ww / (1.0f + expf(-v.z));
        m.w += ww / (1.0f + expf(-v.w));
    }
    float4 scl = make_float4(1.0f + m.x, 1.0f + m.y, 1.0f + m.z, 1.0f + m.w);
    float4* ob = (float4*)out + (size_t)b * C_ * 16384;
#pragma unroll 8
    for (int c = 0; c < 64; c++) {
        float4 v = base[(size_t)c * 16384 + p4];
        v.x *= scl.x; v.y *= scl.y; v.z *= scl.z; v.w *= scl.w;
        ob[(size_t)c * 16384 + p4] = v;
    }
}

extern "C" void kernel_launch(void* const* d_in, const int* in_sizes, int n_in,
                              void* d_out, int out_size) {
    const float* fp  = (const float*)d_in[0];
    const float* fms = (const float*)d_in[1];
    if (n_in >= 2 && in_sizes[0] == B_ * C_ * 256) {
        fp  = (const float*)d_in[1];
        fms = (const float*)d_in[0];
    }
    float* out = (float*)d_out;

    tables_kernel  <<<1, 256>>>();
    bigpass_kernel <<<8192 + 512, 256>>>(fp);
    reduce_kernel  <<<NBC, 256>>>();
    histB_kernel   <<<512, 256>>>();
    ms_kernel      <<<NBC, 256>>>(fms);
    parow_kernel   <<<B_, 256>>>();
    joint_kernel   <<<NBC, 256>>>();
    relms_kernel   <<<B_, 256>>>(fms, out);
    smat_kernel    <<<NBC, 256>>>(fms);
    grpsel_kernel  <<<1, 512>>>();
    final_kernel   <<<NBC, 256>>>(fp, out);
}

// round 8
// speedup vs baseline: 1.4166x; 1.4166x over previous
#include <cuda_runtime.h>
#include <cuda_bf16.h>
#include <math.h>

#define B_   8
#define C_   64
#define HW   65536
#define NBC  512
#define RELP 33554432

// ---------------- scratch (__device__ globals; no allocations) ----------------
__device__ float g_sum[NBC], g_sumsq[NBC];
__device__ float g_pool[NBC * 256];
__device__ float g_ap[NBC * 256];
__device__ float g_fpm[B_ * HW];
__device__ float g_hp[B_];
__device__ int   g_msbin[NBC * 256];
__device__ int   g_histms[NBC * 256];
__device__ float g_hms[NBC];
__device__ float g_na[NBC], g_meana[NBC];
__device__ int   g_pabin[B_ * 256];
__device__ int   g_histpa[B_ * 256];
__device__ float g_rowsum[B_ * 257];
__device__ float g_mi[NBC];
__device__ float g_mxv[NBC];
__device__ int   g_amx[NBC];
__device__ int   g_mink[1];
__device__ int   g_order[NBC];
__device__ float g_wsel[NBC];
__device__ float g_psum[NBC * 16], g_psumsq[NBC * 16];
__device__ float g_appart[NBC * 16 * 3 * 16];
__device__ float g_fmn[512], g_fmx[512];
__device__ int   g_histB[B_ * 256];
__device__ float g_csum[B_ * 4 * HW];   // per-(b,cg) partial channel sums (8 MB)

// ---- jax half-pixel bilinear 16->256 weights ----
__device__ __forceinline__ void up_pair(int o, int& j0, float& w0, int& j1, float& w1) {
    int i = o >> 4, r = o & 15;
    if (r < 8) {
        float f = (float)(2 * r + 17) * (1.0f / 32.0f);
        if (i == 0) { j0 = 0; w0 = 1.0f; j1 = 0; w1 = 0.0f; }
        else        { j0 = i - 1; w0 = 1.0f - f; j1 = i; w1 = f; }
    } else {
        float f = (float)(2 * r - 15) * (1.0f / 32.0f);
        if (i == 15) { j0 = 15; w0 = 1.0f; j1 = 15; w1 = 0.0f; }
        else         { j0 = i; w0 = 1.0f - f; j1 = i + 1; w1 = f; }
    }
}
__device__ __forceinline__ float up_w(int o, int j) {
    int j0, j1; float w0, w1;
    up_pair(o, j0, w0, j1, w1);
    float r = 0.0f;
    if (j == j0) r += w0;
    if (j == j1) r += w1;
    return r;
}

__device__ __forceinline__ float gfun(float c) {
    float q = c * (1.0f / 65536.0f);
    return -q * logf(fmaxf(q + 1e-8f, 1e-30f));
}
__device__ __forceinline__ int bin255(float v, float mn, float mx) {
    return (int)(__fmul_rn(__fdiv_rn(v - mn, mx - mn), 255.0f));
}

// ========== K1: single-read streaming pass over f_p ==========
// 512 blocks: (b, rowgroup rg, channel-group cg of 16 channels)
__global__ void bigpass_kernel(const float* __restrict__ fp) {
    __shared__ float sv[16 * 257];     // current channel tile (transposed access)
    __shared__ float sh_cs[16 * 256];  // per-channel column sums
    __shared__ float xa[16 * 17];
    __shared__ float wsh[512];
    __shared__ float wy[48];
    __shared__ float sh_p[256];
    __shared__ float sh_w[16 * 8];     // per-channel warp partials of sumsq
    int blk = blockIdx.x;
    int b  = blk >> 6;
    int rg = (blk >> 2) & 15;
    int cg = blk & 3;
    int px = threadIdx.x;

    // local weight tables
    for (int e = px; e < 512; e += 256) {
        int kx = e >> 5, q = e & 31;
        int p = 16 * kx - 8 + q;
        wsh[e] = (p >= 0 && p < 256) ? up_w(p, kx) : 0.0f;
    }
    if (px < 48) {
        int s = px >> 4, o = px & 15;
        int ky = rg - 1 + s;
        wy[px] = (ky >= 0 && ky < 16) ? up_w(rg * 16 + o, ky) : 0.0f;
    }
    // zero g_histB (any 8 blocks; done well before histB kernel launches)
    if (blk < 8) g_histB[blk * 256 + px] = 0;

    float pxsum[16];
#pragma unroll
    for (int r = 0; r < 16; r++) pxsum[r] = 0.0f;

    for (int ci = 0; ci < 16; ci++) {
        int c = cg * 16 + ci;
        int bc = b * 64 + c;
        const float* base = fp + (size_t)bc * HW + rg * 4096;
        float v[16];
#pragma unroll
        for (int r = 0; r < 16; r++) v[r] = base[r * 256 + px];
        float cs = 0.0f, s2 = 0.0f;
#pragma unroll
        for (int r = 0; r < 16; r++) { cs += v[r]; s2 += v[r] * v[r]; pxsum[r] += v[r]; }
        sh_cs[ci * 256 + px] = cs;
        // warp reduce s2 (feeds nb only; order change tolerance-safe)
        float wsum = s2;
#pragma unroll
        for (int off = 16; off > 0; off >>= 1) wsum += __shfl_down_sync(0xffffffffu, wsum, off);
        if ((px & 31) == 0) sh_w[ci * 8 + (px >> 5)] = wsum;
#pragma unroll
        for (int r = 0; r < 16; r++) sv[r * 257 + px] = v[r];
        __syncthreads();                       // sv ready; prev y-combine done
        {
            int o = px & 15, kx = px >> 4;
            int p0 = 16 * kx - 8;
            float acc = 0.0f;
#pragma unroll
            for (int q = 0; q < 32; q++) {
                int p = p0 + q;
                int pc = p < 0 ? 0 : (p > 255 ? 255 : p);
                acc += wsh[kx * 32 + q] * sv[o * 257 + pc];
            }
            xa[kx * 17 + o] = acc;
        }
        __syncthreads();                       // xa ready; sv free for next iter
        if (px < 48) {
            int s = px >> 4, kx = px & 15;
            int ky = rg - 1 + s;
            if (ky >= 0 && ky < 16) {
                float acc = 0.0f;
#pragma unroll
                for (int o = 0; o < 16; o++) acc += wy[s * 16 + o] * xa[kx * 17 + o];
                g_appart[((bc * 16 + rg) * 3 + s) * 16 + kx] = acc;
            }
        }
    }
    __syncthreads();
    // pool rows (EXACT old order: ps = sum_{q=0..15} colsum[kx*16+q]) + psum stage 1
    {
        int ci = px >> 4, kx = px & 15;
        float ps = 0.0f;
#pragma unroll
        for (int q = 0; q < 16; q++) ps += sh_cs[ci * 256 + kx * 16 + q];
        int bc = b * 64 + cg * 16 + ci;
        g_pool[bc * 256 + rg * 16 + kx] = ps;
        sh_p[px] = ps;
    }
    __syncthreads();
    if (px < 16) {
        float s = 0.0f;
#pragma unroll
        for (int k = 0; k < 16; k++) s += sh_p[px * 16 + k];
        g_psum[(b * 64 + cg * 16 + px) * 16 + rg] = s;
    } else if (px >= 32 && px < 48) {
        int cj = px - 32;
        float s = 0.0f;
#pragma unroll
        for (int k = 0; k < 8; k++) s += sh_w[cj * 8 + k];
        g_psumsq[(b * 64 + cg * 16 + cj) * 16 + rg] = s;
    }
    // csum partials (pixel-linear within (b,cg))
#pragma unroll
    for (int r = 0; r < 16; r++)
        g_csum[(size_t)(b * 4 + cg) * HW + rg * 4096 + r * 256 + px] = pxsum[r];
}

// ========== K2: reduce stats partials + assemble fpm + minmax partials ======
__global__ void mid_kernel() {
    int blk = blockIdx.x;
    int t = threadIdx.x;
    if (blk < 512) {
        int bc = blk;
        if (t == 0) {
            float s = 0.0f;
            for (int r = 0; r < 16; r++) s += g_psum[bc * 16 + r];
            g_sum[bc] = s;
        } else if (t == 32) {
            float s = 0.0f;
            for (int r = 0; r < 16; r++) s += g_psumsq[bc * 16 + r];
            g_sumsq[bc] = s;
        }
        int ky = t >> 4;
        float acc = 0.0f;
        if (ky - 1 >= 0) acc += g_appart[((bc * 16 + ky - 1) * 3 + 2) * 16 + (t & 15)];
        acc += g_appart[((bc * 16 + ky) * 3 + 1) * 16 + (t & 15)];
        if (ky + 1 < 16)  acc += g_appart[((bc * 16 + ky + 1) * 3 + 0) * 16 + (t & 15)];
        g_ap[bc * 256 + t] = acc;
    } else {
        __shared__ float ra[256], rb[256];
        int fblk = blk - 512;                 // 0..511
        int idx4 = fblk * 256 + t;            // float4 index into g_fpm
        int b = idx4 >> 14;
        int p4 = idx4 & 16383;
        const float4* cs4 = (const float4*)g_csum;
        float4 s = cs4[(size_t)(b * 4 + 0) * 16384 + p4];
        float4 s1 = cs4[(size_t)(b * 4 + 1) * 16384 + p4];
        float4 s2 = cs4[(size_t)(b * 4 + 2) * 16384 + p4];
        float4 s3 = cs4[(size_t)(b * 4 + 3) * 16384 + p4];
        s.x = ((s.x + s1.x) + s2.x) + s3.x;
        s.y = ((s.y + s1.y) + s2.y) + s3.y;
        s.z = ((s.z + s1.z) + s2.z) + s3.z;
        s.w = ((s.w + s1.w) + s2.w) + s3.w;
        const float inv = 1.0f / 64.0f;
        s.x *= inv; s.y *= inv; s.z *= inv; s.w *= inv;
        ((float4*)g_fpm)[idx4] = s;
        float mn = fminf(fminf(s.x, s.y), fminf(s.z, s.w));
        float mx = fmaxf(fmaxf(s.x, s.y), fmaxf(s.z, s.w));
        ra[t] = mn; rb[t] = mx;
        __syncthreads();
        for (int off = 128; off > 0; off >>= 1) {
            if (t < off) { ra[t] = fminf(ra[t], ra[t + off]); rb[t] = fmaxf(rb[t], rb[t + off]); }
            __syncthreads();
        }
        if (t == 0) { g_fmn[fblk] = ra[0]; g_fmx[fblk] = rb[0]; }
    }
}

// ========== K3: parallel per-batch fpm histogram ==========
__global__ void histB_kernel() {
    int blk = blockIdx.x;                  // 512 blocks
    int b = blk >> 6, chunk = blk & 63;
    int t = threadIdx.x;
    __shared__ float ra[64], rb[64];
    __shared__ int hist[256];
    if (t < 64) { ra[t] = g_fmn[b * 64 + t]; rb[t] = g_fmx[b * 64 + t]; }
    hist[t] = 0;
    __syncthreads();
    if (t < 32) { ra[t] = fminf(ra[t], ra[t + 32]); rb[t] = fmaxf(rb[t], rb[t + 32]); }
    __syncthreads();
    if (t < 16) { ra[t] = fminf(ra[t], ra[t + 16]); rb[t] = fmaxf(rb[t], rb[t + 16]); }
    __syncthreads();
    if (t < 8) { ra[t] = fminf(ra[t], ra[t + 8]); rb[t] = fmaxf(rb[t], rb[t + 8]); }
    __syncthreads();
    if (t < 4) { ra[t] = fminf(ra[t], ra[t + 4]); rb[t] = fmaxf(rb[t], rb[t + 4]); }
    __syncthreads();
    if (t < 2) { ra[t] = fminf(ra[t], ra[t + 2]); rb[t] = fmaxf(rb[t], rb[t + 2]); }
    __syncthreads();
    if (t == 0) { ra[0] = fminf(ra[0], ra[1]); rb[0] = fmaxf(rb[0], rb[1]); }
    __syncthreads();
    float mn = ra[0], mx = rb[0];
    const float* base = g_fpm + b * HW + chunk * 1024;
#pragma unroll
    for (int i = 0; i < 4; i++) {
        float v = base[i * 256 + t];
        atomicAdd(&hist[bin255(v, mn, mx)], 1);
    }
    __syncthreads();
    if (hist[t] > 0) atomicAdd(&g_histB[b * 256 + t], hist[t]);
}

// ========== K4: ms binning + entropy + Gram moments + similarity (merged) ====
__global__ void mssmat_kernel(const float* __restrict__ fms) {
    int bc = blockIdx.x, t = threadIdx.x;
    int b = bc >> 6;
    __shared__ float sv[256];
    __shared__ float ra[256], rb[256];
    __shared__ int hist[256];
    __shared__ float Gsh[256], Nsh[256];
    __shared__ float sap[32 * 257];
    __shared__ float val[64];
    float v = fms[bc * 256 + t];
    sv[t] = v;
    // local Gram entry: G[i][j] = sum_o w(o,i) w(o,j), nonzero only |i-j|<=1
    {
        int i = t >> 4, j = t & 15;
        float g = 0.0f;
        int d = i - j; if (d < 0) d = -d;
        if (d <= 1) {
            int mnij = i < j ? i : j, mxij = i < j ? j : i;
            int lo = 16 * mnij - 8; if (lo < 0) lo = 0;
            int hi = 16 * mxij + 24; if (hi > 256) hi = 256;
            for (int o = lo; o < hi; o++) g += up_w(o, i) * up_w(o, j);
        }
        Gsh[t] = g;
    }
    ra[t] = v; rb[t] = v; __syncthreads();
    for (int off = 128; off > 0; off >>= 1) {
        if (t < off) { ra[t] = fminf(ra[t], ra[t + off]); rb[t] = fmaxf(rb[t], rb[t + off]); }
        __syncthreads();
    }
    float mn = ra[0], mx = rb[0];
    int bin = bin255(v, mn, mx);
    g_msbin[bc * 256 + t] = bin;
    hist[t] = 0; __syncthreads();
    atomicAdd(&hist[bin], 1); __syncthreads();
    g_histms[bc * 256 + t] = hist[t];
    float p = hist[t] * (1.0f / 256.0f);
    ra[t] = -p * logf(p + 1e-8f);
    __syncthreads();
    for (int off = 128; off > 0; off >>= 1) { if (t < off) ra[t] += ra[t + off]; __syncthreads(); }
    if (t == 0) g_hms[bc] = ra[0];
    __syncthreads();
    // Gram moments
    int i = t >> 4, j = t & 15;
    float n = 0.0f;
#pragma unroll
    for (int k = 0; k < 16; k++) n += sv[i * 16 + k] * Gsh[k * 16 + j];
    Nsh[t] = n;
    __syncthreads();
    float pp = 0.0f;
#pragma unroll
    for (int k = 0; k < 16; k++) pp += Nsh[i * 16 + k] * sv[j * 16 + k];
    ra[t] = Gsh[t] * pp;
    rb[t] = sv[t];
    __syncthreads();
    for (int off = 128; off > 0; off >>= 1) {
        if (t < off) { ra[t] += ra[t + off]; rb[t] += rb[t + off]; }
        __syncthreads();
    }
    __shared__ float s_meana, s_na;
    if (t == 0) {
        float SU2 = ra[0];
        float SU = 256.0f * rb[0];
        s_meana = SU * (1.0f / 65536.0f);
        s_na = __fsqrt_rn(SU2 - SU * SU * (1.0f / 65536.0f));
        g_meana[bc] = s_meana;
        g_na[bc] = s_na;
    }
    __syncthreads();
    // similarity: dots of ms (=sv) against ap rows, 2 halves
    float meana = s_meana;
    for (int h = 0; h < 2; h++) {
        __syncthreads();
        for (int ii = 0; ii < 32; ii++)
            sap[ii * 257 + t] = g_ap[(size_t)(b * 64 + h * 32 + ii) * 256 + t];
        __syncthreads();
        if ((t >> 5) == h && t < 64) {
            int row = t & 31;
            float dot = 0.0f;
#pragma unroll 8
            for (int k = 0; k < 256; k++) dot += sv[k] * sap[row * 257 + k];
            val[t] = dot - meana * g_sum[b * 64 + t];
        }
    }
    __syncthreads();
    if (t == 0) {
        float mxv = val[0]; int am = 0;
        for (int d = 1; d < 64; d++) if (val[d] > mxv) { mxv = val[d]; am = d; }
        float nb = __fsqrt_rn(g_sumsq[bc] - g_sum[bc] * g_sum[bc] * (1.0f / 65536.0f));
        float den = __fmul_rn(s_na * nb, 0.01f);
        g_mxv[bc] = __fdiv_rn(mxv, den);
        g_amx[bc] = am;
    }
}

// ========== K5: f_p_a binning + rowsum table + hp entropy ==========
__global__ void parow_kernel() {
    int b = blockIdx.x, t = threadIdx.x;
    __shared__ float ra[256], rb[256];
    __shared__ int hist[256];
    __shared__ float gts[513];
    float val = 0.0f;
    for (int c = 0; c < 64; c++) val += g_pool[(b * 64 + c) * 256 + t] * (1.0f / 256.0f);
    val *= (1.0f / 64.0f);
    for (int e = t; e < 513; e += 256) gts[e] = gfun((float)(e - 256));
    ra[t] = val; rb[t] = val; __syncthreads();
    for (int off = 128; off > 0; off >>= 1) {
        if (t < off) { ra[t] = fminf(ra[t], ra[t + off]); rb[t] = fmaxf(rb[t], rb[t + off]); }
        __syncthreads();
    }
    float mn = ra[0], mx = rb[0];
    int bin = bin255(val, mn, mx);
    g_pabin[b * 256 + t] = bin;
    hist[t] = 0; __syncthreads();
    atomicAdd(&hist[bin], 1); __syncthreads();
    g_histpa[b * 256 + t] = hist[t];
    float pB = (float)g_histB[b * 256 + t] * (1.0f / 65536.0f);
    ra[t] = -pB * logf(pB + 1e-8f);
    __syncthreads();
    for (int off = 128; off > 0; off >>= 1) { if (t < off) ra[t] += ra[t + off]; __syncthreads(); }
    if (t == 0) g_hp[b] = ra[0];
    __syncthreads();
    float acc = 0.0f;
    for (int j = 0; j < 256; j++) acc += gts[512 - t - hist[j]];
    g_rowsum[b * 257 + t] = acc;
    if (t == 0) {
        float a2 = 0.0f;
        for (int j = 0; j < 256; j++) a2 += gts[256 - hist[j]];
        g_rowsum[b * 257 + 256] = a2;
    }
}

// ========== K6: joint entropy + mi ==========
__global__ void joint_kernel() {
    int bc = blockIdx.x, t = threadIdx.x;
    int b = bc >> 6;
    __shared__ int keys[256];
    __shared__ float red[256];
    __shared__ float gts[513];
    int u = g_msbin[bc * 256 + t];
    int v = g_pabin[b * 256 + t];
    keys[t] = u * 256 + v;
    for (int e = t; e < 513; e += 256) gts[e] = gfun((float)(e - 256));
    __syncthreads();
    float acc = g_rowsum[b * 257 + g_histms[bc * 256 + t]];
    int my = keys[t], J = 0; bool first = true;
    for (int q = 0; q < 256; q++) {
        int k = keys[q];
        if (k == my) { J++; if (q < t) first = false; }
    }
    if (first) {
        int hm = g_histms[bc * 256 + u];
        int hp = g_histpa[b * 256 + v];
        int cold = 256 - hm - hp;
        acc += gts[cold + 2 * J + 256] - gts[cold + 256];
    }
    red[t] = acc; __syncthreads();
    for (int off = 128; off > 0; off >>= 1) { if (t < off) red[t] += red[t + off]; __syncthreads(); }
    if (t == 0) g_mi[bc] = g_hp[b] + g_hms[bc] - red[0];
}

// ========== K7: rel_ms output (blocks 0..7) + group selection (block 8) =====
__global__ void relgrp_kernel(const float* __restrict__ fms, float* __restrict__ out) {
    int t = threadIdx.x;   // 512 threads
    if (blockIdx.x < 8) {
        int b = blockIdx.x;
        __shared__ float mi[64];
        if (t < 64) mi[t] = g_mi[b * 64 + t];
        __syncthreads();
        if (t == 0) {
            float mx = mi[0];
            for (int c = 1; c < 64; c++) mx = fmaxf(mx, mi[c]);
            float s = 0.0f;
            for (int c = 0; c < 64; c++) { mi[c] = expf(mi[c] - mx); s += mi[c]; }
            float inv = 1.0f / s;
            for (int c = 0; c < 64; c++) mi[c] *= inv;
        }
        __syncthreads();
        if (t < 256) {
            for (int c = 0; c < 64; c++) {
                int idx = (b * 64 + c) * 256 + t;
                float vv = fms[idx];
                out[RELP + idx] = vv + vv * mi[c];
            }
        }
    } else {
        int b = t >> 6, i = t & 63;
        __shared__ float sc[8][64], gsh[8][64], sortedv[8][64];
        __shared__ int csh[8][64];
        __shared__ int uniq[8];
        __shared__ int mk;
        sc[b][i] = g_mxv[b * 64 + i];
        gsh[b][i] = 0.0f; csh[b][i] = 0;
        __syncthreads();
        if (i == 0) {
            float mx = sc[b][0];
            for (int c = 1; c < 64; c++) mx = fmaxf(mx, sc[b][c]);
            float s = 0.0f;
            for (int c = 0; c < 64; c++) { sc[b][c] = expf(sc[b][c] - mx); s += sc[b][c]; }
            float inv = 1.0f / s;
            for (int c = 0; c < 64; c++) sc[b][c] *= inv;
        }
        __syncthreads();
        int idx = g_amx[b * 64 + i];
        atomicAdd(&gsh[b][idx], sc[b][i]);
        atomicAdd(&csh[b][idx], 1);
        __syncthreads();
        if (i == 0) {
            int u = 0;
            for (int j = 0; j < 64; j++) u += (csh[b][j] > 0) ? 1 : 0;
            uniq[b] = u;
        }
        __syncthreads();
        if (t == 0) {
            int m = uniq[0];
            for (int q = 1; q < 8; q++) m = min(m, uniq[q]);
            mk = (m + 1) >> 1;
            g_mink[0] = mk;
        }
        float vi = gsh[b][i];
        int r = 0;
        for (int j = 0; j < 64; j++) {
            float vj = gsh[b][j];
            if (vj > vi || (vj == vi && j < i)) r++;
        }
        g_order[b * 64 + r] = i;
        sortedv[b][r] = vi;
        __syncthreads();
        if (i == 0) {
            int m = mk;
            float mx = sortedv[b][0];
            float s = 0.0f;
            for (int q = 0; q < m; q++) { float e = expf(sortedv[b][q] - mx); sortedv[b][q] = e; s += e; }
            float inv = 1.0f / s;
            for (int q = 0; q < m; q++) g_wsel[b * 64 + q] = sortedv[b][q] * inv;
            for (int q = m; q < 64; q++) g_wsel[b * 64 + q] = 0.0f;
        }
    }
}

// ========== K8: fused mask + rel_p output (float4) ==========
__global__ void final_kernel(const float* __restrict__ fp, float* __restrict__ out) {
    int blk = blockIdx.x;
    int b = blk >> 6;
    int p4 = ((blk & 63) << 8) | threadIdx.x;
    __shared__ int mk;
    __shared__ int ord[32];
    __shared__ float w[32];
    if (threadIdx.x == 0) mk = g_mink[0];
    if (threadIdx.x < 32) {
        ord[threadIdx.x] = g_order[b * 64 + threadIdx.x];
        w[threadIdx.x] = g_wsel[b * 64 + threadIdx.x];
    }
    __syncthreads();
    const float4* base = (const float4*)fp + (size_t)b * C_ * 16384;
    float4 m = make_float4(0.f, 0.f, 0.f, 0.f);
    int mkk = mk;
    for (int r = 0; r < mkk; r++) {
        float4 v = base[(size_t)ord[r] * 16384 + p4];
        float ww = w[r];
        m.x += ww / (1.0f + expf(-v.x));
        m.y += ww / (1.0f + expf(-v.y));
        m.z += ww / (1.0f + expf(-v.z));
        m.w += ww / (1.0f + expf(-v.w));
    }
    float4 scl = make_float4(1.0f + m.x, 1.0f + m.y, 1.0f + m.z, 1.0f + m.w);
    float4* ob = (float4*)out + (size_t)b * C_ * 16384;
#pragma unroll 8
    for (int c = 0; c < 64; c++) {
        float4 v = base[(size_t)c * 16384 + p4];
        v.x *= scl.x; v.y *= scl.y; v.z *= scl.z; v.w *= scl.w;
        ob[(size_t)c * 16384 + p4] = v;
    }
}

extern "C" void kernel_launch(void* const* d_in, const int* in_sizes, int n_in,
                              void* d_out, int out_size) {
    const float* fp  = (const float*)d_in[0];
    const float* fms = (const float*)d_in[1];
    if (n_in >= 2 && in_sizes[0] == B_ * C_ * 256) {
        fp  = (const float*)d_in[1];
        fms = (const float*)d_in[0];
    }
    float* out = (float*)d_out;

    bigpass_kernel <<<512, 256>>>(fp);
    mid_kernel     <<<1024, 256>>>();
    histB_kernel   <<<512, 256>>>();
    mssmat_kernel  <<<NBC, 256>>>(fms);
    parow_kernel   <<<B_, 256>>>();
    joint_kernel   <<<NBC, 256>>>();
    relgrp_kernel  <<<9, 512>>>(fms, out);
    final_kernel   <<<NBC, 256>>>(fp, out);
}

// round 9
// speedup vs baseline: 1.4940x; 1.0546x over previous
#include <cuda_runtime.h>
#include <cuda_bf16.h>
#include <math.h>

#define B_   8
#define C_   64
#define HW   65536
#define NBC  512
#define RELP 33554432

// ---------------- scratch (__device__ globals; no allocations) ----------------
__device__ float g_sum[NBC], g_sumsq[NBC];
__device__ float g_pool[NBC * 256];
__device__ float g_ap[NBC * 256];
__device__ float g_fpm[B_ * HW];
__device__ float g_hp[B_];
__device__ int   g_msbin[NBC * 256];
__device__ int   g_histms[NBC * 256];
__device__ float g_hms[NBC];
__device__ float g_na[NBC], g_meana[NBC];
__device__ int   g_pabin[B_ * 256];
__device__ int   g_histpa[B_ * 256];
__device__ float g_rowsum[B_ * 257];
__device__ float g_mi[NBC];
__device__ float g_mxv[NBC];
__device__ int   g_amx[NBC];
__device__ int   g_mink[1];
__device__ int   g_order[NBC];
__device__ float g_wsel[NBC];
__device__ float g_psum[NBC * 16], g_psumsq[NBC * 16];
__device__ float g_appart[NBC * 16 * 3 * 16];
__device__ float g_fmn[512], g_fmx[512];
__device__ int   g_histB[B_ * 256];
__device__ float g_csum[B_ * 4 * HW];   // per-(b,cg) partial channel sums (8 MB)

// ---- jax half-pixel bilinear 16->256 weights ----
__device__ __forceinline__ void up_pair(int o, int& j0, float& w0, int& j1, float& w1) {
    int i = o >> 4, r = o & 15;
    if (r < 8) {
        float f = (float)(2 * r + 17) * (1.0f / 32.0f);
        if (i == 0) { j0 = 0; w0 = 1.0f; j1 = 0; w1 = 0.0f; }
        else        { j0 = i - 1; w0 = 1.0f - f; j1 = i; w1 = f; }
    } else {
        float f = (float)(2 * r - 15) * (1.0f / 32.0f);
        if (i == 15) { j0 = 15; w0 = 1.0f; j1 = 15; w1 = 0.0f; }
        else         { j0 = i; w0 = 1.0f - f; j1 = i + 1; w1 = f; }
    }
}
__device__ __forceinline__ float up_w(int o, int j) {
    int j0, j1; float w0, w1;
    up_pair(o, j0, w0, j1, w1);
    float r = 0.0f;
    if (j == j0) r += w0;
    if (j == j1) r += w1;
    return r;
}

__device__ __forceinline__ float gfun(float c) {
    float q = c * (1.0f / 65536.0f);
    return -q * logf(fmaxf(q + 1e-8f, 1e-30f));
}
__device__ __forceinline__ int bin255(float v, float mn, float mx) {
    return (int)(__fmul_rn(__fdiv_rn(v - mn, mx - mn), 255.0f));
}
__device__ __forceinline__ float wredsum(float x) {
#pragma unroll
    for (int o = 16; o > 0; o >>= 1) x += __shfl_xor_sync(0xffffffffu, x, o);
    return x;
}

// ========== K1: single-read streaming pass over f_p ==========
__global__ void bigpass_kernel(const float* __restrict__ fp) {
    __shared__ float sv[16 * 257];
    __shared__ float sh_cs[16 * 256];
    __shared__ float xa[16 * 17];
    __shared__ float wsh[512];
    __shared__ float wy[48];
    __shared__ float sh_p[256];
    __shared__ float sh_w[16 * 8];
    int blk = blockIdx.x;
    int b  = blk >> 6;
    int rg = (blk >> 2) & 15;
    int cg = blk & 3;
    int px = threadIdx.x;

    for (int e = px; e < 512; e += 256) {
        int kx = e >> 5, q = e & 31;
        int p = 16 * kx - 8 + q;
        wsh[e] = (p >= 0 && p < 256) ? up_w(p, kx) : 0.0f;
    }
    if (px < 48) {
        int s = px >> 4, o = px & 15;
        int ky = rg - 1 + s;
        wy[px] = (ky >= 0 && ky < 16) ? up_w(rg * 16 + o, ky) : 0.0f;
    }
    if (blk < 8) g_histB[blk * 256 + px] = 0;

    float pxsum[16];
#pragma unroll
    for (int r = 0; r < 16; r++) pxsum[r] = 0.0f;

    for (int ci = 0; ci < 16; ci++) {
        int c = cg * 16 + ci;
        int bc = b * 64 + c;
        const float* base = fp + (size_t)bc * HW + rg * 4096;
        float v[16];
#pragma unroll
        for (int r = 0; r < 16; r++) v[r] = base[r * 256 + px];
        float cs = 0.0f, s2 = 0.0f;
#pragma unroll
        for (int r = 0; r < 16; r++) { cs += v[r]; s2 += v[r] * v[r]; pxsum[r] += v[r]; }
        sh_cs[ci * 256 + px] = cs;
        float wsum = wredsum(s2);
        if ((px & 31) == 0) sh_w[ci * 8 + (px >> 5)] = wsum;
#pragma unroll
        for (int r = 0; r < 16; r++) sv[r * 257 + px] = v[r];
        __syncthreads();
        {
            int o = px & 15, kx = px >> 4;
            int p0 = 16 * kx - 8;
            float acc = 0.0f;
#pragma unroll
            for (int q = 0; q < 32; q++) {
                int p = p0 + q;
                int pc = p < 0 ? 0 : (p > 255 ? 255 : p);
                acc += wsh[kx * 32 + q] * sv[o * 257 + pc];
            }
            xa[kx * 17 + o] = acc;
        }
        __syncthreads();
        if (px < 48) {
            int s = px >> 4, kx = px & 15;
            int ky = rg - 1 + s;
            if (ky >= 0 && ky < 16) {
                float acc = 0.0f;
#pragma unroll
                for (int o = 0; o < 16; o++) acc += wy[s * 16 + o] * xa[kx * 17 + o];
                g_appart[((bc * 16 + rg) * 3 + s) * 16 + kx] = acc;
            }
        }
    }
    __syncthreads();
    {
        int ci = px >> 4, kx = px & 15;
        float ps = 0.0f;
#pragma unroll
        for (int q = 0; q < 16; q++) ps += sh_cs[ci * 256 + kx * 16 + q];
        int bc = b * 64 + cg * 16 + ci;
        g_pool[bc * 256 + rg * 16 + kx] = ps;
        sh_p[px] = ps;
    }
    __syncthreads();
    if (px < 16) {
        float s = 0.0f;
#pragma unroll
        for (int k = 0; k < 16; k++) s += sh_p[px * 16 + k];
        g_psum[(b * 64 + cg * 16 + px) * 16 + rg] = s;
    } else if (px >= 32 && px < 48) {
        int cj = px - 32;
        float s = 0.0f;
#pragma unroll
        for (int k = 0; k < 8; k++) s += sh_w[cj * 8 + k];
        g_psumsq[(b * 64 + cg * 16 + cj) * 16 + rg] = s;
    }
#pragma unroll
    for (int r = 0; r < 16; r++)
        g_csum[(size_t)(b * 4 + cg) * HW + rg * 4096 + r * 256 + px] = pxsum[r];
}

// ========== K2: reduce stats partials + assemble fpm + minmax partials ======
__global__ void mid_kernel() {
    int blk = blockIdx.x;
    int t = threadIdx.x;
    if (blk < 512) {
        int bc = blk;
        if (t == 0) {
            float s = 0.0f;
            for (int r = 0; r < 16; r++) s += g_psum[bc * 16 + r];
            g_sum[bc] = s;
        } else if (t == 32) {
            float s = 0.0f;
            for (int r = 0; r < 16; r++) s += g_psumsq[bc * 16 + r];
            g_sumsq[bc] = s;
        }
        int ky = t >> 4;
        float acc = 0.0f;
        if (ky - 1 >= 0) acc += g_appart[((bc * 16 + ky - 1) * 3 + 2) * 16 + (t & 15)];
        acc += g_appart[((bc * 16 + ky) * 3 + 1) * 16 + (t & 15)];
        if (ky + 1 < 16)  acc += g_appart[((bc * 16 + ky + 1) * 3 + 0) * 16 + (t & 15)];
        g_ap[bc * 256 + t] = acc;
    } else {
        __shared__ float ra[8], rb[8];
        int fblk = blk - 512;
        int idx4 = fblk * 256 + t;
        int b = idx4 >> 14;
        int p4 = idx4 & 16383;
        const float4* cs4 = (const float4*)g_csum;
        float4 s = cs4[(size_t)(b * 4 + 0) * 16384 + p4];
        float4 s1 = cs4[(size_t)(b * 4 + 1) * 16384 + p4];
        float4 s2 = cs4[(size_t)(b * 4 + 2) * 16384 + p4];
        float4 s3 = cs4[(size_t)(b * 4 + 3) * 16384 + p4];
        s.x = ((s.x + s1.x) + s2.x) + s3.x;
        s.y = ((s.y + s1.y) + s2.y) + s3.y;
        s.z = ((s.z + s1.z) + s2.z) + s3.z;
        s.w = ((s.w + s1.w) + s2.w) + s3.w;
        const float inv = 1.0f / 64.0f;
        s.x *= inv; s.y *= inv; s.z *= inv; s.w *= inv;
        ((float4*)g_fpm)[idx4] = s;
        float mn = fminf(fminf(s.x, s.y), fminf(s.z, s.w));
        float mx = fmaxf(fmaxf(s.x, s.y), fmaxf(s.z, s.w));
#pragma unroll
        for (int o = 16; o > 0; o >>= 1) {
            mn = fminf(mn, __shfl_xor_sync(0xffffffffu, mn, o));
            mx = fmaxf(mx, __shfl_xor_sync(0xffffffffu, mx, o));
        }
        if ((t & 31) == 0) { ra[t >> 5] = mn; rb[t >> 5] = mx; }
        __syncthreads();
        if (t == 0) {
            for (int q = 1; q < 8; q++) { mn = fminf(ra[0], ra[q]); ra[0] = mn; mx = fmaxf(rb[0], rb[q]); rb[0] = mx; }
            g_fmn[fblk] = ra[0]; g_fmx[fblk] = rb[0];
        }
    }
}

// ========== K3: histB (blocks 0..511) + mssmat (blocks 512..1023) ==========
__global__ void hist_mssmat_kernel(const float* __restrict__ fms) {
    int blk = blockIdx.x;
    int t = threadIdx.x;
    if (blk < 512) {
        // ---- per-batch fpm histogram chunk ----
        int b = blk >> 6, chunk = blk & 63;
        __shared__ float ra[64], rb[64];
        __shared__ int hist[256];
        if (t < 64) { ra[t] = g_fmn[b * 64 + t]; rb[t] = g_fmx[b * 64 + t]; }
        hist[t] = 0;
        __syncthreads();
        if (t < 32) {
            float mn = fminf(ra[t], ra[t + 32]);
            float mx = fmaxf(rb[t], rb[t + 32]);
#pragma unroll
            for (int o = 16; o > 0; o >>= 1) {
                mn = fminf(mn, __shfl_xor_sync(0xffffffffu, mn, o));
                mx = fmaxf(mx, __shfl_xor_sync(0xffffffffu, mx, o));
            }
            if (t == 0) { ra[0] = mn; rb[0] = mx; }
        }
        __syncthreads();
        float mn = ra[0], mx = rb[0];
        const float* base = g_fpm + b * HW + chunk * 1024;
#pragma unroll
        for (int i = 0; i < 4; i++) {
            float v = base[i * 256 + t];
            atomicAdd(&hist[bin255(v, mn, mx)], 1);
        }
        __syncthreads();
        if (hist[t] > 0) atomicAdd(&g_histB[b * 256 + t], hist[t]);
    } else {
        // ---- ms binning + entropy + Gram moments + similarity ----
        int bc = blk - 512;
        int b = bc >> 6;
        int lane = t & 31, wid = t >> 5;
        __shared__ float sv[256];
        __shared__ float Gsh[256], Nsh[256];
        __shared__ int hist[256];
        __shared__ float val[64];
        __shared__ float wr1[8], wr2[8];
        __shared__ float s_mn, s_mx, s_meana, s_na;
        float v = fms[bc * 256 + t];
        sv[t] = v;
        hist[t] = 0;
        {
            int i = t >> 4, j = t & 15;
            float g = 0.0f;
            int d = i - j; if (d < 0) d = -d;
            if (d <= 1) {
                int mnij = i < j ? i : j, mxij = i < j ? j : i;
                int lo = 16 * mnij - 8; if (lo < 0) lo = 0;
                int hi = 16 * mxij + 24; if (hi > 256) hi = 256;
                for (int o = lo; o < hi; o++) g += up_w(o, i) * up_w(o, j);
            }
            Gsh[t] = g;
        }
        // min/max via shuffles
        float mn = v, mx = v;
#pragma unroll
        for (int o = 16; o > 0; o >>= 1) {
            mn = fminf(mn, __shfl_xor_sync(0xffffffffu, mn, o));
            mx = fmaxf(mx, __shfl_xor_sync(0xffffffffu, mx, o));
        }
        if (lane == 0) { wr1[wid] = mn; wr2[wid] = mx; }
        __syncthreads();                                   // (1) also hist=0, sv, Gsh ready
        if (t == 0) {
            for (int q = 1; q < 8; q++) { wr1[0] = fminf(wr1[0], wr1[q]); wr2[0] = fmaxf(wr2[0], wr2[q]); }
            s_mn = wr1[0]; s_mx = wr2[0];
        }
        __syncthreads();                                   // (2)
        int bin = bin255(v, s_mn, s_mx);
        g_msbin[bc * 256 + t] = bin;
        atomicAdd(&hist[bin], 1);
        __syncthreads();                                   // (3)
        int h = hist[t];
        g_histms[bc * 256 + t] = h;
        float p = h * (1.0f / 256.0f);
        float ent = wredsum(-p * logf(p + 1e-8f));
        if (lane == 0) wr1[wid] = ent;
        // Gram moments: N = M*G
        {
            int i = t >> 4, j = t & 15;
            float n = 0.0f;
#pragma unroll
            for (int k = 0; k < 16; k++) n += sv[i * 16 + k] * Gsh[k * 16 + j];
            Nsh[t] = n;
        }
        __syncthreads();                                   // (4)
        if (t == 0) {
            float s = 0.0f;
            for (int q = 0; q < 8; q++) s += wr1[q];
            g_hms[bc] = s;
        }
        float pp = 0.0f;
        {
            int i = t >> 4, j = t & 15;
#pragma unroll
            for (int k = 0; k < 16; k++) pp += Nsh[i * 16 + k] * sv[j * 16 + k];
        }
        float t1 = wredsum(Gsh[t] * pp);
        float t2 = wredsum(v);
        __syncthreads();                                   // (5) wr1 free
        if (lane == 0) { wr1[wid] = t1; wr2[wid] = t2; }
        __syncthreads();                                   // (6)
        if (t == 0) {
            float SU2 = 0.0f, SM = 0.0f;
            for (int q = 0; q < 8; q++) { SU2 += wr1[q]; SM += wr2[q]; }
            float SU = 256.0f * SM;
            s_meana = SU * (1.0f / 65536.0f);
            s_na = __fsqrt_rn(SU2 - SU * SU * (1.0f / 65536.0f));
            g_meana[bc] = s_meana;
            g_na[bc] = s_na;
        }
        __syncthreads();                                   // (7)
        // similarity dots: warp wid handles rows wid*8..wid*8+7 (direct L2 reads)
        float meana = s_meana;
#pragma unroll
        for (int rr = 0; rr < 8; rr++) {
            int row = wid * 8 + rr;
            const float* ap = g_ap + (size_t)(b * 64 + row) * 256;
            float d = 0.0f;
#pragma unroll
            for (int q = 0; q < 8; q++) d += sv[lane + 32 * q] * ap[lane + 32 * q];
            d = wredsum(d);
            if (lane == 0) val[row] = d - meana * g_sum[b * 64 + row];
        }
        __syncthreads();                                   // (8)
        if (t == 0) {
            float mxv = val[0]; int am = 0;
            for (int d = 1; d < 64; d++) if (val[d] > mxv) { mxv = val[d]; am = d; }
            float nb = __fsqrt_rn(g_sumsq[bc] - g_sum[bc] * g_sum[bc] * (1.0f / 65536.0f));
            float den = __fmul_rn(s_na * nb, 0.01f);
            g_mxv[bc] = __fdiv_rn(mxv, den);
            g_amx[bc] = am;
        }
    }
}

// ========== K5: f_p_a binning + rowsum table + hp entropy ==========
__global__ void parow_kernel() {
    int b = blockIdx.x, t = threadIdx.x;
    __shared__ float ra[256], rb[256];
    __shared__ int hist[256];
    __shared__ float gts[513];
    float val = 0.0f;
    for (int c = 0; c < 64; c++) val += g_pool[(b * 64 + c) * 256 + t] * (1.0f / 256.0f);
    val *= (1.0f / 64.0f);
    for (int e = t; e < 513; e += 256) gts[e] = gfun((float)(e - 256));
    ra[t] = val; rb[t] = val; __syncthreads();
    for (int off = 128; off > 0; off >>= 1) {
        if (t < off) { ra[t] = fminf(ra[t], ra[t + off]); rb[t] = fmaxf(rb[t], rb[t + off]); }
        __syncthreads();
    }
    float mn = ra[0], mx = rb[0];
    int bin = bin255(val, mn, mx);
    g_pabin[b * 256 + t] = bin;
    hist[t] = 0; __syncthreads();
    atomicAdd(&hist[bin], 1); __syncthreads();
    g_histpa[b * 256 + t] = hist[t];
    float pB = (float)g_histB[b * 256 + t] * (1.0f / 65536.0f);
    ra[t] = -pB * logf(pB + 1e-8f);
    __syncthreads();
    for (int off = 128; off > 0; off >>= 1) { if (t < off) ra[t] += ra[t + off]; __syncthreads(); }
    if (t == 0) g_hp[b] = ra[0];
    __syncthreads();
    float acc = 0.0f;
    const int4* h4 = (const int4*)hist;
#pragma unroll 8
    for (int j4 = 0; j4 < 64; j4++) {
        int4 hh = h4[j4];
        acc += gts[512 - t - hh.x] + gts[512 - t - hh.y] + gts[512 - t - hh.z] + gts[512 - t - hh.w];
    }
    g_rowsum[b * 257 + t] = acc;
    if (t == 0) {
        float a2 = 0.0f;
        for (int j = 0; j < 256; j++) a2 += gts[256 - hist[j]];
        g_rowsum[b * 257 + 256] = a2;
    }
}

// ========== K6: joint entropy + mi ==========
__global__ void joint_kernel() {
    int bc = blockIdx.x, t = threadIdx.x;
    int b = bc >> 6;
    int lane = t & 31, wid = t >> 5;
    __shared__ int keys[256];
    __shared__ float gts[513];
    __shared__ float wr[8];
    int u = g_msbin[bc * 256 + t];
    int v = g_pabin[b * 256 + t];
    keys[t] = u * 256 + v;
    for (int e = t; e < 513; e += 256) gts[e] = gfun((float)(e - 256));
    __syncthreads();
    float acc = g_rowsum[b * 257 + g_histms[bc * 256 + t]];
    int my = keys[t], J = 0; bool first = true;
    const int4* k4 = (const int4*)keys;
#pragma unroll 4
    for (int q4 = 0; q4 < 64; q4++) {
        int4 kk = k4[q4];
        int qb = q4 << 2;
        if (kk.x == my) { J++; if (qb < t) first = false; }
        if (kk.y == my) { J++; if (qb + 1 < t) first = false; }
        if (kk.z == my) { J++; if (qb + 2 < t) first = false; }
        if (kk.w == my) { J++; if (qb + 3 < t) first = false; }
    }
    if (first) {
        int hm = g_histms[bc * 256 + u];
        int hp = g_histpa[b * 256 + v];
        int cold = 256 - hm - hp;
        acc += gts[cold + 2 * J + 256] - gts[cold + 256];
    }
    acc = wredsum(acc);
    if (lane == 0) wr[wid] = acc;
    __syncthreads();
    if (t == 0) {
        float s = 0.0f;
        for (int q = 0; q < 8; q++) s += wr[q];
        g_mi[bc] = g_hp[b] + g_hms[bc] - s;
    }
}

// ========== K7: rel_ms output (blocks 0..7) + group selection (block 8) =====
__global__ void relgrp_kernel(const float* __restrict__ fms, float* __restrict__ out) {
    int t = threadIdx.x;   // 512 threads
    if (blockIdx.x < 8) {
        int b = blockIdx.x;
        __shared__ float mi[64];
        if (t < 64) mi[t] = g_mi[b * 64 + t];
        __syncthreads();
        if (t == 0) {
            float mx = mi[0];
            for (int c = 1; c < 64; c++) mx = fmaxf(mx, mi[c]);
            float s = 0.0f;
            for (int c = 0; c < 64; c++) { mi[c] = expf(mi[c] - mx); s += mi[c]; }
            float inv = 1.0f / s;
            for (int c = 0; c < 64; c++) mi[c] *= inv;
        }
        __syncthreads();
        if (t < 256) {
            for (int c = 0; c < 64; c++) {
                int idx = (b * 64 + c) * 256 + t;
                float vv = fms[idx];
                out[RELP + idx] = vv + vv * mi[c];
            }
        }
    } else {
        int b = t >> 6, i = t & 63;
        __shared__ float sc[8][64], gsh[8][64], sortedv[8][64];
        __shared__ int csh[8][64];
        __shared__ int uniq[8];
        __shared__ int mk;
        sc[b][i] = g_mxv[b * 64 + i];
        gsh[b][i] = 0.0f; csh[b][i] = 0;
        __syncthreads();
        if (i == 0) {
            float mx = sc[b][0];
            for (int c = 1; c < 64; c++) mx = fmaxf(mx, sc[b][c]);
            float s = 0.0f;
            for (int c = 0; c < 64; c++) { sc[b][c] = expf(sc[b][c] - mx); s += sc[b][c]; }
            float inv = 1.0f / s;
            for (int c = 0; c < 64; c++) sc[b][c] *= inv;
        }
        __syncthreads();
        int idx = g_amx[b * 64 + i];
        atomicAdd(&gsh[b][idx], sc[b][i]);
        atomicAdd(&csh[b][idx], 1);
        __syncthreads();
        if (i == 0) {
            int u = 0;
            for (int j = 0; j < 64; j++) u += (csh[b][j] > 0) ? 1 : 0;
            uniq[b] = u;
        }
        __syncthreads();
        if (t == 0) {
            int m = uniq[0];
            for (int q = 1; q < 8; q++) m = min(m, uniq[q]);
            mk = (m + 1) >> 1;
            g_mink[0] = mk;
        }
        float vi = gsh[b][i];
        int r = 0;
        for (int j = 0; j < 64; j++) {
            float vj = gsh[b][j];
            if (vj > vi || (vj == vi && j < i)) r++;
        }
        g_order[b * 64 + r] = i;
        sortedv[b][r] = vi;
        __syncthreads();
        if (i == 0) {
            int m = mk;
            float mx = sortedv[b][0];
            float s = 0.0f;
            for (int q = 0; q < m; q++) { float e = expf(sortedv[b][q] - mx); sortedv[b][q] = e; s += e; }
            float inv = 1.0f / s;
            for (int q = 0; q < m; q++) g_wsel[b * 64 + q] = sortedv[b][q] * inv;
            for (int q = m; q < 64; q++) g_wsel[b * 64 + q] = 0.0f;
        }
    }
}

// ========== K8: fused mask + rel_p output (float4) ==========
__global__ void final_kernel(const float* __restrict__ fp, float* __restrict__ out) {
    int blk = blockIdx.x;
    int b = blk >> 6;
    int p4 = ((blk & 63) << 8) | threadIdx.x;
    __shared__ int mk;
    __shared__ int ord[32];
    __shared__ float w[32];
    if (threadIdx.x == 0) mk = g_mink[0];
    if (threadIdx.x < 32) {
        ord[threadIdx.x] = g_order[b * 64 + threadIdx.x];
        w[threadIdx.x] = g_wsel[b * 64 + threadIdx.x];
    }
    __syncthreads();
    const float4* base = (const float4*)fp + (size_t)b * C_ * 16384;
    float4 m = make_float4(0.f, 0.f, 0.f, 0.f);
    int mkk = mk;
    for (int r = 0; r < mkk; r++) {
        float4 v = base[(size_t)ord[r] * 16384 + p4];
        float ww = w[r];
        m.x += ww / (1.0f + expf(-v.x));
        m.y += ww / (1.0f + expf(-v.y));
        m.z += ww / (1.0f + expf(-v.z));
        m.w += ww / (1.0f + expf(-v.w));
    }
    float4 scl = make_float4(1.0f + m.x, 1.0f + m.y, 1.0f + m.z, 1.0f + m.w);
    float4* ob = (float4*)out + (size_t)b * C_ * 16384;
#pragma unroll 8
    for (int c = 0; c < 64; c++) {
        float4 v = base[(size_t)c * 16384 + p4];
        v.x *= scl.x; v.y *= scl.y; v.z *= scl.z; v.w *= scl.w;
        ob[(size_t)c * 16384 + p4] = v;
    }
}

extern "C" void kernel_launch(void* const* d_in, const int* in_sizes, int n_in,
                              void* d_out, int out_size) {
    const float* fp  = (const float*)d_in[0];
    const float* fms = (const float*)d_in[1];
    if (n_in >= 2 && in_sizes[0] == B_ * C_ * 256) {
        fp  = (const float*)d_in[1];
        fms = (const float*)d_in[0];
    }
    float* out = (float*)d_out;

    bigpass_kernel     <<<512, 256>>>(fp);
    mid_kernel         <<<1024, 256>>>();
    hist_mssmat_kernel <<<1024, 256>>>(fms);
    parow_kernel       <<<B_, 256>>>();
    joint_kernel       <<<NBC, 256>>>();
    relgrp_kernel      <<<9, 512>>>(fms, out);
    final_kernel       <<<NBC, 256>>>(fp, out);
}

// round 11
// speedup vs baseline: 1.5747x; 1.0541x over previous
#include <cuda_runtime.h>
#include <cuda_bf16.h>
#include <math.h>

#define B_   8
#define C_   64
#define HW   65536
#define NBC  512
#define RELP 33554432

// ---------------- scratch (__device__ globals; no allocations) ----------------
__device__ float g_sum[NBC], g_sumsq[NBC];
__device__ float g_pool[NBC * 256];
__device__ float g_ap[NBC * 256];
__device__ float g_fpm[B_ * HW];
__device__ float g_hp[B_];
__device__ int   g_msbin[NBC * 256];
__device__ int   g_histms[NBC * 256];
__device__ float g_hms[NBC];
__device__ float g_na[NBC], g_meana[NBC];
__device__ int   g_pabin[B_ * 256];
__device__ int   g_histpa[B_ * 256];
__device__ float g_rowsum[B_ * 257];
__device__ float g_mi[NBC];
__device__ float g_mxv[NBC];
__device__ int   g_amx[NBC];
__device__ int   g_mink[1];
__device__ int   g_order[NBC];
__device__ float g_wsel[NBC];
__device__ float g_psum[NBC * 16], g_psumsq[NBC * 16];
__device__ float g_appart[NBC * 16 * 3 * 16];
__device__ float g_fmn[512], g_fmx[512];
__device__ int   g_histB[B_ * 256];
__device__ float g_csum[B_ * 4 * HW];   // per-(b,cg) partial channel sums (8 MB)

// ---- jax half-pixel bilinear 16->256 weights ----
__device__ __forceinline__ void up_pair(int o, int& j0, float& w0, int& j1, float& w1) {
    int i = o >> 4, r = o & 15;
    if (r < 8) {
        float f = (float)(2 * r + 17) * (1.0f / 32.0f);
        if (i == 0) { j0 = 0; w0 = 1.0f; j1 = 0; w1 = 0.0f; }
        else        { j0 = i - 1; w0 = 1.0f - f; j1 = i; w1 = f; }
    } else {
        float f = (float)(2 * r - 15) * (1.0f / 32.0f);
        if (i == 15) { j0 = 15; w0 = 1.0f; j1 = 15; w1 = 0.0f; }
        else         { j0 = i; w0 = 1.0f - f; j1 = i + 1; w1 = f; }
    }
}
__device__ __forceinline__ float up_w(int o, int j) {
    int j0, j1; float w0, w1;
    up_pair(o, j0, w0, j1, w1);
    float r = 0.0f;
    if (j == j0) r += w0;
    if (j == j1) r += w1;
    return r;
}

__device__ __forceinline__ float gfun(float c) {
    float q = c * (1.0f / 65536.0f);
    return -q * logf(fmaxf(q + 1e-8f, 1e-30f));
}
__device__ __forceinline__ int bin255(float v, float mn, float mx) {
    return (int)(__fmul_rn(__fdiv_rn(v - mn, mx - mn), 255.0f));
}
__device__ __forceinline__ float wredsum(float x) {
#pragma unroll
    for (int o = 16; o > 0; o >>= 1) x += __shfl_xor_sync(0xffffffffu, x, o);
    return x;
}

// ========== K1: single-read streaming pass over f_p ==========
__global__ void bigpass_kernel(const float* __restrict__ fp) {
    __shared__ float sv[16 * 257];
    __shared__ float sh_cs[16 * 256];
    __shared__ float xa[16 * 17];
    __shared__ float wsh[512];
    __shared__ float wy[48];
    __shared__ float sh_p[256];
    __shared__ float sh_w[16 * 8];
    int blk = blockIdx.x;
    int b  = blk >> 6;
    int rg = (blk >> 2) & 15;
    int cg = blk & 3;
    int px = threadIdx.x;

    for (int e = px; e < 512; e += 256) {
        int kx = e >> 5, q = e & 31;
        int p = 16 * kx - 8 + q;
        wsh[e] = (p >= 0 && p < 256) ? up_w(p, kx) : 0.0f;
    }
    if (px < 48) {
        int s = px >> 4, o = px & 15;
        int ky = rg - 1 + s;
        wy[px] = (ky >= 0 && ky < 16) ? up_w(rg * 16 + o, ky) : 0.0f;
    }
    if (blk < 8) g_histB[blk * 256 + px] = 0;

    float pxsum[16];
#pragma unroll
    for (int r = 0; r < 16; r++) pxsum[r] = 0.0f;

    for (int ci = 0; ci < 16; ci++) {
        int c = cg * 16 + ci;
        int bc = b * 64 + c;
        const float* base = fp + (size_t)bc * HW + rg * 4096;
        float v[16];
#pragma unroll
        for (int r = 0; r < 16; r++) v[r] = base[r * 256 + px];
        float cs = 0.0f, s2 = 0.0f;
#pragma unroll
        for (int r = 0; r < 16; r++) { cs += v[r]; s2 += v[r] * v[r]; pxsum[r] += v[r]; }
        sh_cs[ci * 256 + px] = cs;
        float wsum = wredsum(s2);
        if ((px & 31) == 0) sh_w[ci * 8 + (px >> 5)] = wsum;
#pragma unroll
        for (int r = 0; r < 16; r++) sv[r * 257 + px] = v[r];
        __syncthreads();
        {
            int o = px & 15, kx = px >> 4;
            int p0 = 16 * kx - 8;
            float acc = 0.0f;
#pragma unroll
            for (int q = 0; q < 32; q++) {
                int p = p0 + q;
                int pc = p < 0 ? 0 : (p > 255 ? 255 : p);
                acc += wsh[kx * 32 + q] * sv[o * 257 + pc];
            }
            xa[kx * 17 + o] = acc;
        }
        __syncthreads();
        if (px < 48) {
            int s = px >> 4, kx = px & 15;
            int ky = rg - 1 + s;
            if (ky >= 0 && ky < 16) {
                float acc = 0.0f;
#pragma unroll
                for (int o = 0; o < 16; o++) acc += wy[s * 16 + o] * xa[kx * 17 + o];
                g_appart[((bc * 16 + rg) * 3 + s) * 16 + kx] = acc;
            }
        }
    }
    __syncthreads();
    {
        int ci = px >> 4, kx = px & 15;
        float ps = 0.0f;
#pragma unroll
        for (int q = 0; q < 16; q++) ps += sh_cs[ci * 256 + kx * 16 + q];
        int bc = b * 64 + cg * 16 + ci;
        g_pool[bc * 256 + rg * 16 + kx] = ps;
        sh_p[px] = ps;
    }
    __syncthreads();
    if (px < 16) {
        float s = 0.0f;
#pragma unroll
        for (int k = 0; k < 16; k++) s += sh_p[px * 16 + k];
        g_psum[(b * 64 + cg * 16 + px) * 16 + rg] = s;
    } else if (px >= 32 && px < 48) {
        int cj = px - 32;
        float s = 0.0f;
#pragma unroll
        for (int k = 0; k < 8; k++) s += sh_w[cj * 8 + k];
        g_psumsq[(b * 64 + cg * 16 + cj) * 16 + rg] = s;
    }
#pragma unroll
    for (int r = 0; r < 16; r++)
        g_csum[(size_t)(b * 4 + cg) * HW + rg * 4096 + r * 256 + px] = pxsum[r];
}

// ========== K2: reduce stats partials + assemble fpm + minmax partials ======
__global__ void mid_kernel() {
    int blk = blockIdx.x;
    int t = threadIdx.x;
    if (blk < 512) {
        int bc = blk;
        if (t == 0) {
            float s = 0.0f;
            for (int r = 0; r < 16; r++) s += g_psum[bc * 16 + r];
            g_sum[bc] = s;
        } else if (t == 32) {
            float s = 0.0f;
            for (int r = 0; r < 16; r++) s += g_psumsq[bc * 16 + r];
            g_sumsq[bc] = s;
        }
        int ky = t >> 4;
        float acc = 0.0f;
        if (ky - 1 >= 0) acc += g_appart[((bc * 16 + ky - 1) * 3 + 2) * 16 + (t & 15)];
        acc += g_appart[((bc * 16 + ky) * 3 + 1) * 16 + (t & 15)];
        if (ky + 1 < 16)  acc += g_appart[((bc * 16 + ky + 1) * 3 + 0) * 16 + (t & 15)];
        g_ap[bc * 256 + t] = acc;
    } else {
        __shared__ float ra[8], rb[8];
        int fblk = blk - 512;
        int idx4 = fblk * 256 + t;
        int b = idx4 >> 14;
        int p4 = idx4 & 16383;
        const float4* cs4 = (const float4*)g_csum;
        float4 s = cs4[(size_t)(b * 4 + 0) * 16384 + p4];
        float4 s1 = cs4[(size_t)(b * 4 + 1) * 16384 + p4];
        float4 s2 = cs4[(size_t)(b * 4 + 2) * 16384 + p4];
        float4 s3 = cs4[(size_t)(b * 4 + 3) * 16384 + p4];
        s.x = ((s.x + s1.x) + s2.x) + s3.x;
        s.y = ((s.y + s1.y) + s2.y) + s3.y;
        s.z = ((s.z + s1.z) + s2.z) + s3.z;
        s.w = ((s.w + s1.w) + s2.w) + s3.w;
        const float inv = 1.0f / 64.0f;
        s.x *= inv; s.y *= inv; s.z *= inv; s.w *= inv;
        ((float4*)g_fpm)[idx4] = s;
        float mn = fminf(fminf(s.x, s.y), fminf(s.z, s.w));
        float mx = fmaxf(fmaxf(s.x, s.y), fmaxf(s.z, s.w));
#pragma unroll
        for (int o = 16; o > 0; o >>= 1) {
            mn = fminf(mn, __shfl_xor_sync(0xffffffffu, mn, o));
            mx = fmaxf(mx, __shfl_xor_sync(0xffffffffu, mx, o));
        }
        if ((t & 31) == 0) { ra[t >> 5] = mn; rb[t >> 5] = mx; }
        __syncthreads();
        if (t == 0) {
            for (int q = 1; q < 8; q++) { mn = fminf(ra[0], ra[q]); ra[0] = mn; mx = fmaxf(rb[0], rb[q]); rb[0] = mx; }
            g_fmn[fblk] = ra[0]; g_fmx[fblk] = rb[0];
        }
    }
}

// ========== K3: histB (blocks 0..511) + mssmat (blocks 512..1023) ==========
__global__ void hist_mssmat_kernel(const float* __restrict__ fms) {
    int blk = blockIdx.x;
    int t = threadIdx.x;
    if (blk < 512) {
        int b = blk >> 6, chunk = blk & 63;
        __shared__ float ra[64], rb[64];
        __shared__ __align__(16) int hist[256];
        if (t < 64) { ra[t] = g_fmn[b * 64 + t]; rb[t] = g_fmx[b * 64 + t]; }
        hist[t] = 0;
        __syncthreads();
        if (t < 32) {
            float mn = fminf(ra[t], ra[t + 32]);
            float mx = fmaxf(rb[t], rb[t + 32]);
#pragma unroll
            for (int o = 16; o > 0; o >>= 1) {
                mn = fminf(mn, __shfl_xor_sync(0xffffffffu, mn, o));
                mx = fmaxf(mx, __shfl_xor_sync(0xffffffffu, mx, o));
            }
            if (t == 0) { ra[0] = mn; rb[0] = mx; }
        }
        __syncthreads();
        float mn = ra[0], mx = rb[0];
        const float* base = g_fpm + b * HW + chunk * 1024;
#pragma unroll
        for (int i = 0; i < 4; i++) {
            float v = base[i * 256 + t];
            atomicAdd(&hist[bin255(v, mn, mx)], 1);
        }
        __syncthreads();
        if (hist[t] > 0) atomicAdd(&g_histB[b * 256 + t], hist[t]);
    } else {
        int bc = blk - 512;
        int b = bc >> 6;
        int lane = t & 31, wid = t >> 5;
        __shared__ float sv[256];
        __shared__ float Gsh[256], Nsh[256];
        __shared__ __align__(16) int hist[256];
        __shared__ float val[64];
        __shared__ float wr1[8], wr2[8];
        __shared__ float s_mn, s_mx, s_meana, s_na;
        float v = fms[bc * 256 + t];
        sv[t] = v;
        hist[t] = 0;
        {
            int i = t >> 4, j = t & 15;
            float g = 0.0f;
            int d = i - j; if (d < 0) d = -d;
            if (d <= 1) {
                int mnij = i < j ? i : j, mxij = i < j ? j : i;
                int lo = 16 * mnij - 8; if (lo < 0) lo = 0;
                int hi = 16 * mxij + 24; if (hi > 256) hi = 256;
                for (int o = lo; o < hi; o++) g += up_w(o, i) * up_w(o, j);
            }
            Gsh[t] = g;
        }
        float mn = v, mx = v;
#pragma unroll
        for (int o = 16; o > 0; o >>= 1) {
            mn = fminf(mn, __shfl_xor_sync(0xffffffffu, mn, o));
            mx = fmaxf(mx, __shfl_xor_sync(0xffffffffu, mx, o));
        }
        if (lane == 0) { wr1[wid] = mn; wr2[wid] = mx; }
        __syncthreads();
        if (t == 0) {
            for (int q = 1; q < 8; q++) { wr1[0] = fminf(wr1[0], wr1[q]); wr2[0] = fmaxf(wr2[0], wr2[q]); }
            s_mn = wr1[0]; s_mx = wr2[0];
        }
        __syncthreads();
        int bin = bin255(v, s_mn, s_mx);
        g_msbin[bc * 256 + t] = bin;
        atomicAdd(&hist[bin], 1);
        __syncthreads();
        int h = hist[t];
        g_histms[bc * 256 + t] = h;
        float p = h * (1.0f / 256.0f);
        float ent = wredsum(-p * logf(p + 1e-8f));
        if (lane == 0) wr1[wid] = ent;
        {
            int i = t >> 4, j = t & 15;
            float n = 0.0f;
#pragma unroll
            for (int k = 0; k < 16; k++) n += sv[i * 16 + k] * Gsh[k * 16 + j];
            Nsh[t] = n;
        }
        __syncthreads();
        if (t == 0) {
            float s = 0.0f;
            for (int q = 0; q < 8; q++) s += wr1[q];
            g_hms[bc] = s;
        }
        float pp = 0.0f;
        {
            int i = t >> 4, j = t & 15;
#pragma unroll
            for (int k = 0; k < 16; k++) pp += Nsh[i * 16 + k] * sv[j * 16 + k];
        }
        float t1 = wredsum(Gsh[t] * pp);
        float t2 = wredsum(v);
        __syncthreads();
        if (lane == 0) { wr1[wid] = t1; wr2[wid] = t2; }
        __syncthreads();
        if (t == 0) {
            float SU2 = 0.0f, SM = 0.0f;
            for (int q = 0; q < 8; q++) { SU2 += wr1[q]; SM += wr2[q]; }
            float SU = 256.0f * SM;
            s_meana = SU * (1.0f / 65536.0f);
            s_na = __fsqrt_rn(SU2 - SU * SU * (1.0f / 65536.0f));
            g_meana[bc] = s_meana;
            g_na[bc] = s_na;
        }
        __syncthreads();
        float meana = s_meana;
#pragma unroll
        for (int rr = 0; rr < 8; rr++) {
            int row = wid * 8 + rr;
            const float* ap = g_ap + (size_t)(b * 64 + row) * 256;
            float d = 0.0f;
#pragma unroll
            for (int q = 0; q < 8; q++) d += sv[lane + 32 * q] * ap[lane + 32 * q];
            d = wredsum(d);
            if (lane == 0) val[row] = d - meana * g_sum[b * 64 + row];
        }
        __syncthreads();
        if (t == 0) {
            float mxv = val[0]; int am = 0;
            for (int d = 1; d < 64; d++) if (val[d] > mxv) { mxv = val[d]; am = d; }
            float nb = __fsqrt_rn(g_sumsq[bc] - g_sum[bc] * g_sum[bc] * (1.0f / 65536.0f));
            float den = __fmul_rn(s_na * nb, 0.01f);
            g_mxv[bc] = __fdiv_rn(mxv, den);
            g_amx[bc] = am;
        }
    }
}

// ========== K4: parow (blocks 0..7, 512 thr) + grpsel (block 8) ==========
__global__ void parow_grpsel_kernel() {
    int t = threadIdx.x;   // 512 threads
    if (blockIdx.x < 8) {
        int b = blockIdx.x;
        __shared__ float ra[256], rb[256];
        __shared__ __align__(16) int hist[256];
        __shared__ float gts[513];
        float val = 0.0f;
        if (t < 256) {
            for (int c = 0; c < 64; c++) val += g_pool[(b * 64 + c) * 256 + t] * (1.0f / 256.0f);
            val *= (1.0f / 64.0f);
            ra[t] = val; rb[t] = val; hist[t] = 0;
        }
        for (int e = t; e < 513; e += 512) gts[e] = gfun((float)(e - 256));
        __syncthreads();
        for (int off = 128; off > 0; off >>= 1) {
            if (t < off) { ra[t] = fminf(ra[t], ra[t + off]); rb[t] = fmaxf(rb[t], rb[t + off]); }
            __syncthreads();
        }
        float mn = ra[0], mx = rb[0];
        if (t < 256) {
            int bin = bin255(val, mn, mx);
            g_pabin[b * 256 + t] = bin;
            atomicAdd(&hist[bin], 1);
        }
        __syncthreads();
        if (t < 256) {
            g_histpa[b * 256 + t] = hist[t];
            float pB = (float)g_histB[b * 256 + t] * (1.0f / 65536.0f);
            ra[t] = -pB * logf(pB + 1e-8f);
        }
        __syncthreads();
        for (int off = 128; off > 0; off >>= 1) {
            if (t < off) ra[t] += ra[t + off];
            __syncthreads();
        }
        if (t == 0) g_hp[b] = ra[0];
        if (t <= 256) {
            float acc = 0.0f;
            const int4* h4 = (const int4*)hist;
#pragma unroll 8
            for (int j4 = 0; j4 < 64; j4++) {
                int4 hh = h4[j4];
                acc += gts[512 - t - hh.x] + gts[512 - t - hh.y] + gts[512 - t - hh.z] + gts[512 - t - hh.w];
            }
            g_rowsum[b * 257 + t] = acc;
        }
    } else {
        int b = t >> 6, i = t & 63;
        __shared__ float sc[8][64], gsh[8][64], sortedv[8][64];
        __shared__ int csh[8][64];
        __shared__ int uniq[8];
        __shared__ int mk;
        sc[b][i] = g_mxv[b * 64 + i];
        gsh[b][i] = 0.0f; csh[b][i] = 0;
        __syncthreads();
        if (i == 0) {
            float mx = sc[b][0];
            for (int c = 1; c < 64; c++) mx = fmaxf(mx, sc[b][c]);
            float s = 0.0f;
            for (int c = 0; c < 64; c++) { sc[b][c] = expf(sc[b][c] - mx); s += sc[b][c]; }
            float inv = 1.0f / s;
            for (int c = 0; c < 64; c++) sc[b][c] *= inv;
        }
        __syncthreads();
        int idx = g_amx[b * 64 + i];
        atomicAdd(&gsh[b][idx], sc[b][i]);
        atomicAdd(&csh[b][idx], 1);
        __syncthreads();
        if (i == 0) {
            int u = 0;
            for (int j = 0; j < 64; j++) u += (csh[b][j] > 0) ? 1 : 0;
            uniq[b] = u;
        }
        __syncthreads();
        if (t == 0) {
            int m = uniq[0];
            for (int q = 1; q < 8; q++) m = min(m, uniq[q]);
            mk = (m + 1) >> 1;
            g_mink[0] = mk;
        }
        float vi = gsh[b][i];
        int r = 0;
        for (int j = 0; j < 64; j++) {
            float vj = gsh[b][j];
            if (vj > vi || (vj == vi && j < i)) r++;
        }
        g_order[b * 64 + r] = i;
        sortedv[b][r] = vi;
        __syncthreads();
        if (i == 0) {
            int m = mk;
            float mx = sortedv[b][0];
            float s = 0.0f;
            for (int q = 0; q < m; q++) { float e = expf(sortedv[b][q] - mx); sortedv[b][q] = e; s += e; }
            float inv = 1.0f / s;
            for (int q = 0; q < m; q++) g_wsel[b * 64 + q] = sortedv[b][q] * inv;
            for (int q = m; q < 64; q++) g_wsel[b * 64 + q] = 0.0f;
        }
    }
}

// ========== K5: final (blocks 0..511) + joint (blocks 512..1023) ==========
__global__ void joint_final_kernel(const float* __restrict__ fp, float* __restrict__ out) {
    int t = threadIdx.x;
    if (blockIdx.x < 512) {
        // ---- fused mask + rel_p output (float4) ----
        int blk = blockIdx.x;
        int b = blk >> 6;
        int p4 = ((blk & 63) << 8) | t;
        __shared__ int mk;
        __shared__ int ord[32];
        __shared__ float w[32];
        if (t == 0) mk = g_mink[0];
        if (t < 32) {
            ord[t] = g_order[b * 64 + t];
            w[t] = g_wsel[b * 64 + t];
        }
        __syncthreads();
        const float4* base = (const float4*)fp + (size_t)b * C_ * 16384;
        float4 m = make_float4(0.f, 0.f, 0.f, 0.f);
        int mkk = mk;
        for (int r = 0; r < mkk; r++) {
            float4 v = base[(size_t)ord[r] * 16384 + p4];
            float ww = w[r];
            m.x += ww / (1.0f + expf(-v.x));
            m.y += ww / (1.0f + expf(-v.y));
            m.z += ww / (1.0f + expf(-v.z));
            m.w += ww / (1.0f + expf(-v.w));
        }
        float4 scl = make_float4(1.0f + m.x, 1.0f + m.y, 1.0f + m.z, 1.0f + m.w);
        float4* ob = (float4*)out + (size_t)b * C_ * 16384;
#pragma unroll 8
        for (int c = 0; c < 64; c++) {
            float4 v = base[(size_t)c * 16384 + p4];
            v.x *= scl.x; v.y *= scl.y; v.z *= scl.z; v.w *= scl.w;
            ob[(size_t)c * 16384 + p4] = v;
        }
    } else {
        // ---- joint entropy + mi ----
        int bc = blockIdx.x - 512;
        int b = bc >> 6;
        int lane = t & 31, wid = t >> 5;
        __shared__ __align__(16) int keys[256];
        __shared__ float gts[513];
        __shared__ float wr[8];
        int u = g_msbin[bc * 256 + t];
        int v = g_pabin[b * 256 + t];
        keys[t] = u * 256 + v;
        for (int e = t; e < 513; e += 256) gts[e] = gfun((float)(e - 256));
        __syncthreads();
        float acc = g_rowsum[b * 257 + g_histms[bc * 256 + t]];
        int my = keys[t], J = 0; bool first = true;
        const int4* k4 = (const int4*)keys;
#pragma unroll 4
        for (int q4 = 0; q4 < 64; q4++) {
            int4 kk = k4[q4];
            int qb = q4 << 2;
            if (kk.x == my) { J++; if (qb < t) first = false; }
            if (kk.y == my) { J++; if (qb + 1 < t) first = false; }
            if (kk.z == my) { J++; if (qb + 2 < t) first = false; }
            if (kk.w == my) { J++; if (qb + 3 < t) first = false; }
        }
        if (first) {
            int hm = g_histms[bc * 256 + u];
            int hp = g_histpa[b * 256 + v];
            int cold = 256 - hm - hp;
            acc += gts[cold + 2 * J + 256] - gts[cold + 256];
        }
        acc = wredsum(acc);
        if (lane == 0) wr[wid] = acc;
        __syncthreads();
        if (t == 0) {
            float s = 0.0f;
            for (int q = 0; q < 8; q++) s += wr[q];
            g_mi[bc] = g_hp[b] + g_hms[bc] - s;
        }
    }
}

// ========== K6: softmax(mi) + rel_ms output ==========
__global__ void relms_kernel(const float* __restrict__ fms, float* __restrict__ out) {
    int b = blockIdx.x, t = threadIdx.x;
    __shared__ float mi[64];
    if (t < 64) mi[t] = g_mi[b * 64 + t];
    __syncthreads();
    if (t == 0) {
        float mx = mi[0];
        for (int c = 1; c < 64; c++) mx = fmaxf(mx, mi[c]);
        float s = 0.0f;
        for (int c = 0; c < 64; c++) { mi[c] = expf(mi[c] - mx); s += mi[c]; }
        float inv = 1.0f / s;
        for (int c = 0; c < 64; c++) mi[c] *= inv;
    }
    __syncthreads();
    for (int c = 0; c < 64; c++) {
        int idx = (b * 64 + c) * 256 + t;
        float vv = fms[idx];
        out[RELP + idx] = vv + vv * mi[c];
    }
}

extern "C" void kernel_launch(void* const* d_in, const int* in_sizes, int n_in,
                              void* d_out, int out_size) {
    const float* fp  = (const float*)d_in[0];
    const float* fms = (const float*)d_in[1];
    if (n_in >= 2 && in_sizes[0] == B_ * C_ * 256) {
        fp  = (const float*)d_in[1];
        fms = (const float*)d_in[0];
    }
    float* out = (float*)d_out;

    bigpass_kernel      <<<512, 256>>>(fp);
    mid_kernel          <<<1024, 256>>>();
    hist_mssmat_kernel  <<<1024, 256>>>(fms);
    parow_grpsel_kernel <<<9, 512>>>();
    joint_final_kernel  <<<1024, 256>>>(fp, out);
    relms_kernel        <<<B_, 256>>>(fms, out);
}